// round 4
// baseline (speedup 1.0000x reference)
#include <cuda_runtime.h>
#include <cstdint>

#define T_STEPS 4096
#define BATCH   64
#define NH      128
#define NROWS   (BATCH * T_STEPS)   // 262144
#define NSEG    16
#define SEG_T   (T_STEPS / NSEG)    // 256 steps per segment

// Scratch (allocation-free rule: __device__ globals).
// g_xp padded by 8 steps so the scan's register-ring prefetch never branches.
__device__ float g_xp[((size_t)NROWS + 8) * NH];
__device__ float g_h [(size_t)NROWS * NH];
__device__ float g_hstate[BATCH * NH];      // h carried across segments

// ---------------------------------------------------------------------------
// Helpers
// ---------------------------------------------------------------------------
__device__ __forceinline__ uint64_t ffma2(uint64_t a, uint64_t b, uint64_t c) {
    uint64_t d;
    asm("fma.rn.f32x2 %0, %1, %2, %3;" : "=l"(d) : "l"(a), "l"(b), "l"(c));
    return d;
}
__device__ __forceinline__ float f2sum(uint64_t v) {
    float lo = __uint_as_float((uint32_t)v);
    float hi = __uint_as_float((uint32_t)(v >> 32));
    return lo + hi;
}
__device__ __forceinline__ void cp_async16(uint32_t saddr, const void* g) {
    asm volatile("cp.async.cg.shared.global [%0], [%1], 16;" :: "r"(saddr), "l"(g));
}
__device__ __forceinline__ void cp_commit() { asm volatile("cp.async.commit_group;"); }
__device__ __forceinline__ void cp_wait1()  { asm volatile("cp.async.wait_group 1;" ::: "memory"); }

// ---------------------------------------------------------------------------
// GEMM chunk: one time-segment for all 64 batch rows.
// Grid = 128 blocks: b = blk>>1, half = blk&1; 128 rows per block.
// out[row, j] = (relu?)( sum_i in[row, i] * W[j, woff+i] + bias[j] )
// Thread j owns W row j in registers. 16-row chunks, double-buffered cp.async.
// ---------------------------------------------------------------------------
#define CH 16   // rows per smem chunk
#define RPB 128 // rows per block

template<bool RELU>
__global__ void __launch_bounds__(128, 2) gemm_chunk_kernel(
    const float* __restrict__ in, const float* __restrict__ W,
    int wstride, int woff,
    const float* __restrict__ bias, float* __restrict__ out, int seg)
{
    __shared__ __align__(16) float buf[2][CH * NH];   // 2 x 8KB
    const int j = threadIdx.x;
    const int b    = blockIdx.x >> 1;
    const int half = blockIdx.x & 1;
    const size_t base = (size_t)b * T_STEPS + (size_t)seg * SEG_T + (size_t)half * RPB;

    uint64_t w[64];
#pragma unroll
    for (int k = 0; k < 64; k++)
        w[k] = *reinterpret_cast<const uint64_t*>(&W[(size_t)j * wstride + woff + 2 * k]);
    const float bj = bias[j];

    const uint32_t sb = (uint32_t)__cvta_generic_to_shared(&buf[0][0]);
    const float4* gsrc = reinterpret_cast<const float4*>(in + base * NH);
    const int f4_per_chunk = CH * NH / 4;   // 512 float4 per chunk

    // prologue: chunk 0 -> stage 0  (each thread: 4 x 16B, coalesced)
#pragma unroll
    for (int k = 0; k < 4; k++)
        cp_async16(sb + (uint32_t)(j + k * 128) * 16, gsrc + j + k * 128);
    cp_commit();

    const int nch = RPB / CH;   // 8
    for (int c = 0; c < nch; c++) {
        if (c + 1 < nch) {
            const float4* g = gsrc + (size_t)(c + 1) * f4_per_chunk;
            const uint32_t dst = sb + (uint32_t)((c + 1) & 1) * (CH * NH * 4);
#pragma unroll
            for (int k = 0; k < 4; k++)
                cp_async16(dst + (uint32_t)(j + k * 128) * 16, g + j + k * 128);
        }
        cp_commit();
        cp_wait1();
        __syncthreads();

        const float* stage = buf[c & 1];
#pragma unroll 4
        for (int r = 0; r < CH; r++) {
            const float* row = stage + r * NH;
            uint64_t a0 = 0, a1 = 0;
#pragma unroll
            for (int k = 0; k < 32; k++) {
                ulonglong2 hv = *reinterpret_cast<const ulonglong2*>(&row[4 * k]);
                a0 = ffma2(w[2 * k],     hv.x, a0);
                a1 = ffma2(w[2 * k + 1], hv.y, a1);
            }
            float s = f2sum(a0) + f2sum(a1) + bj;
            if (RELU) s = fmaxf(s, 0.0f);
            out[(base + (size_t)c * CH + r) * NH + j] = s;
        }
        __syncthreads();
    }
}

// ---------------------------------------------------------------------------
// Scan segment: 256 steps of h_t = relu(W1h @ h_{t-1} + xp_t).
// 64 blocks (one chain each), 256 threads: col j = tid&127, half = tid>>7.
// Each thread does half the dot (64 MACs = 32 FFMA2); halves combined via
// SMEM. 2 warps/SMSP for latency hiding. xp via 8-deep LDG register ring.
// ---------------------------------------------------------------------------
__global__ void __launch_bounds__(256, 1) rnn_scan_seg_kernel(
    const float* __restrict__ W1, float* __restrict__ hseq, int seg)
{
    __shared__ __align__(16) float hbuf[2][NH];
    __shared__ float part[NH];
    const int tid  = threadIdx.x;
    const int j    = tid & 127;
    const int half = tid >> 7;
    const int b    = blockIdx.x;

    const size_t row0 = (size_t)b * T_STEPS + (size_t)seg * SEG_T;
    const float* xp = g_xp + row0 * NH;
    float*       hs = hseq + row0 * NH;

    // W1h = W1[:, :128]; this thread's k-range = [half*64, half*64+64)
    uint64_t w[32];
    const float* wrow = W1 + (size_t)j * 256 + half * 64;
#pragma unroll
    for (int k = 0; k < 32; k++)
        w[k] = *reinterpret_cast<const uint64_t*>(wrow + 2 * k);

    if (half == 0)
        hbuf[0][j] = (seg == 0) ? 0.0f : g_hstate[b * NH + j];

    float xr[8];
    if (half == 0) {
#pragma unroll
        for (int u = 0; u < 8; u++)
            xr[u] = xp[(size_t)u * NH + j];
    }

    for (int t0 = 0; t0 < SEG_T; t0 += 8) {
#pragma unroll
        for (int u = 0; u < 8; u++) {
            const int t = t0 + u;
            __syncthreads();                        // h_t visible; WAR safe
            const float* hp = hbuf[t & 1] + half * 64;
            uint64_t a0 = 0, a1 = 0;
#pragma unroll
            for (int k = 0; k < 16; k++) {
                ulonglong2 hv = *reinterpret_cast<const ulonglong2*>(&hp[4 * k]);
                a0 = ffma2(w[2 * k],     hv.x, a0);
                a1 = ffma2(w[2 * k + 1], hv.y, a1);
            }
            float ps = f2sum(a0) + f2sum(a1);
            if (half == 1) part[j] = ps;
            __syncthreads();                        // partials visible
            if (half == 0) {
                float s = ps + part[j] + xr[u];
                s = fmaxf(s, 0.0f);
                hbuf[(t + 1) & 1][j] = s;           // next step's input
                hs[(size_t)t * NH + j] = s;         // for output projection
                // refill ring; overrun past segment end reads data that is
                // never consumed (values discarded) and stays in-bounds
                // thanks to the global g_xp padding.
                xr[u] = xp[(size_t)(t + 8) * NH + j];
            }
        }
    }
    __syncthreads();
    if (half == 0)
        g_hstate[b * NH + j] = hbuf[0][j];          // h after 256 steps (even)
}

// ---------------------------------------------------------------------------
// Launch: software-pipelined segments across 3 streams.
//   default: scan seg 0..15 (serial chain)
//   sB:      gemm1 chunks (xp), throttled to 2-segment lookahead
//   sC:      gemm2 chunks (out), trailing the scan
// Fork/join with events — valid under stream capture.
// ---------------------------------------------------------------------------
extern "C" void kernel_launch(void* const* d_in, const int* in_sizes, int n_in,
                              void* d_out, int out_size)
{
    const float* input = (const float*)d_in[0];   // (64, 4096, 128)
    const float* W1    = (const float*)d_in[1];   // (128, 256)
    const float* b1    = (const float*)d_in[2];   // (128,)
    const float* W2    = (const float*)d_in[3];   // (128, 128)
    const float* b2    = (const float*)d_in[4];   // (128,)
    float* out = (float*)d_out;

    float *xp_ptr, *h_ptr;
    cudaGetSymbolAddress((void**)&xp_ptr, g_xp);
    cudaGetSymbolAddress((void**)&h_ptr,  g_h);

    // One-time host-side resource creation (no device memory involved).
    static cudaStream_t sB = nullptr, sC = nullptr;
    static cudaEvent_t eg1[NSEG], es[NSEG], eFork, eB, eC;
    if (sB == nullptr) {
        cudaStreamCreateWithFlags(&sB, cudaStreamNonBlocking);
        cudaStreamCreateWithFlags(&sC, cudaStreamNonBlocking);
        for (int i = 0; i < NSEG; i++) {
            cudaEventCreateWithFlags(&eg1[i], cudaEventDisableTiming);
            cudaEventCreateWithFlags(&es[i],  cudaEventDisableTiming);
        }
        cudaEventCreateWithFlags(&eFork, cudaEventDisableTiming);
        cudaEventCreateWithFlags(&eB,    cudaEventDisableTiming);
        cudaEventCreateWithFlags(&eC,    cudaEventDisableTiming);
    }

    // Fork side streams off the (captured) default stream.
    cudaEventRecord(eFork, 0);
    cudaStreamWaitEvent(sB, eFork, 0);
    cudaStreamWaitEvent(sC, eFork, 0);

    // Prime gemm1 lookahead: segments 0 and 1.
    gemm_chunk_kernel<false><<<128, 128, 0, sB>>>(input, W1, 256, 128, b1, xp_ptr, 0);
    cudaEventRecord(eg1[0], sB);
    gemm_chunk_kernel<false><<<128, 128, 0, sB>>>(input, W1, 256, 128, b1, xp_ptr, 1);
    cudaEventRecord(eg1[1], sB);

    for (int s = 0; s < NSEG; s++) {
        // scan segment s (default stream) after its xp chunk is ready
        cudaStreamWaitEvent(0, eg1[s], 0);
        rnn_scan_seg_kernel<<<BATCH, 256>>>(W1, h_ptr, s);
        cudaEventRecord(es[s], 0);

        // output projection for segment s trails the scan on sC
        cudaStreamWaitEvent(sC, es[s], 0);
        gemm_chunk_kernel<true><<<128, 128, 0, sC>>>(h_ptr, W2, 128, 0, b2, out, s);

        // gemm1 lookahead: segment s+2, throttled by scan progress
        if (s + 2 < NSEG) {
            cudaStreamWaitEvent(sB, es[s], 0);
            gemm_chunk_kernel<false><<<128, 128, 0, sB>>>(input, W1, 256, 128, b1, xp_ptr, s + 2);
            cudaEventRecord(eg1[s + 2], sB);
        }
    }

    // Join side streams back into the default stream.
    cudaEventRecord(eB, sB);
    cudaEventRecord(eC, sC);
    cudaStreamWaitEvent(0, eB, 0);
    cudaStreamWaitEvent(0, eC, 0);
}

// round 5
// speedup vs baseline: 2.1020x; 2.1020x over previous
#include <cuda_runtime.h>
#include <cstdint>

#define T_STEPS 4096
#define BATCH   64
#define NH      128
#define NROWS   (BATCH * T_STEPS)   // 262144
#define SEGT    2048                // steps per scan half
#define SCAN_SMEM (216 * 1024)      // blocks GEMM CTA co-residency on scan SMs

// Scratch (allocation-free rule: __device__ globals).
// g_xp padded by 8 rows so the scan's register-ring prefetch never branches.
__device__ float g_xp[((size_t)NROWS + 8) * NH];
__device__ float g_h [(size_t)NROWS * NH];
__device__ float g_hstate[BATCH * NH];      // h carried across the two halves

// ---------------------------------------------------------------------------
// Helpers
// ---------------------------------------------------------------------------
__device__ __forceinline__ uint64_t ffma2(uint64_t a, uint64_t b, uint64_t c) {
    uint64_t d;
    asm("fma.rn.f32x2 %0, %1, %2, %3;" : "=l"(d) : "l"(a), "l"(b), "l"(c));
    return d;
}
__device__ __forceinline__ float f2sum(uint64_t v) {
    float lo = __uint_as_float((uint32_t)v);
    float hi = __uint_as_float((uint32_t)(v >> 32));
    return lo + hi;
}
__device__ __forceinline__ void cp_async16(uint32_t saddr, const void* g) {
    asm volatile("cp.async.cg.shared.global [%0], [%1], 16;" :: "r"(saddr), "l"(g));
}
__device__ __forceinline__ void cp_commit() { asm volatile("cp.async.commit_group;"); }
__device__ __forceinline__ void cp_wait1()  { asm volatile("cp.async.wait_group 1;" ::: "memory"); }

// ---------------------------------------------------------------------------
// GEMM over a time range: out[row, j] = (relu?)(sum_i in[row,i]*W[j,woff+i]+bias[j])
// Block -> (b = blk/nchunk, chunk = blk%nchunk), 256 rows per block.
// Thread j owns W row j in registers (64 x f32x2). 16-row smem chunks,
// double-buffered cp.async. 4 accumulators (64-cyc dep chain).
// ---------------------------------------------------------------------------
#define CH  16   // rows per smem stage
#define RPB 256  // rows per block

template<bool RELU>
__global__ void __launch_bounds__(128, 2) gemm128_kernel(
    const float* __restrict__ in, const float* __restrict__ W,
    int wstride, int woff,
    const float* __restrict__ bias, float* __restrict__ out,
    int t_off, int nchunk)
{
    __shared__ __align__(16) float buf[2][CH * NH];   // 2 x 8KB
    const int j  = threadIdx.x;
    const int b  = blockIdx.x / nchunk;
    const int ch = blockIdx.x % nchunk;
    const size_t base = (size_t)b * T_STEPS + (size_t)t_off + (size_t)ch * RPB;

    uint64_t w[64];
#pragma unroll
    for (int k = 0; k < 64; k++)
        w[k] = *reinterpret_cast<const uint64_t*>(&W[(size_t)j * wstride + woff + 2 * k]);
    const float bj = bias[j];

    const uint32_t sb = (uint32_t)__cvta_generic_to_shared(&buf[0][0]);
    const float4* gsrc = reinterpret_cast<const float4*>(in + base * NH);
    const int f4_per_chunk = CH * NH / 4;   // 512 float4 per stage

    // prologue: stage 0
#pragma unroll
    for (int k = 0; k < 4; k++)
        cp_async16(sb + (uint32_t)(j + k * 128) * 16, gsrc + j + k * 128);
    cp_commit();

    const int nch = RPB / CH;   // 16
    for (int c = 0; c < nch; c++) {
        if (c + 1 < nch) {
            const float4* g = gsrc + (size_t)(c + 1) * f4_per_chunk;
            const uint32_t dst = sb + (uint32_t)((c + 1) & 1) * (CH * NH * 4);
#pragma unroll
            for (int k = 0; k < 4; k++)
                cp_async16(dst + (uint32_t)(j + k * 128) * 16, g + j + k * 128);
        }
        cp_commit();
        cp_wait1();
        __syncthreads();

        const float* stage = buf[c & 1];
#pragma unroll 4
        for (int r = 0; r < CH; r++) {
            const float* row = stage + r * NH;
            uint64_t a0 = 0, a1 = 0, a2 = 0, a3 = 0;
#pragma unroll
            for (int k = 0; k < 16; k++) {
                ulonglong2 h0 = *reinterpret_cast<const ulonglong2*>(&row[8 * k]);
                ulonglong2 h1 = *reinterpret_cast<const ulonglong2*>(&row[8 * k + 4]);
                a0 = ffma2(w[4 * k],     h0.x, a0);
                a1 = ffma2(w[4 * k + 1], h0.y, a1);
                a2 = ffma2(w[4 * k + 2], h1.x, a2);
                a3 = ffma2(w[4 * k + 3], h1.y, a3);
            }
            float s = (f2sum(a0) + f2sum(a1)) + (f2sum(a2) + f2sum(a3)) + bj;
            if (RELU) s = fmaxf(s, 0.0f);
            out[(base + (size_t)c * CH + r) * NH + j] = s;
        }
        __syncthreads();
    }
}

// ---------------------------------------------------------------------------
// Scan half: 2048 steps of h_t = relu(W1h @ h_{t-1} + xp_t).
// 64 blocks (one chain each), 128 threads. Thread j owns W1h row j in regs.
// 4 accumulators; h double-buffered in (huge, exclusivity-forcing) dynamic
// smem; xp via 8-deep LDG register ring (no branch thanks to g_xp padding).
// ---------------------------------------------------------------------------
__global__ void __launch_bounds__(128, 1) rnn_scan_kernel(
    const float* __restrict__ W1, float* __restrict__ hseq, int seg)
{
    extern __shared__ __align__(16) float dyn[];
    float (*hbuf)[NH] = reinterpret_cast<float (*)[NH]>(dyn);

    const int j = threadIdx.x;
    const int b = blockIdx.x;

    const size_t row0 = (size_t)b * T_STEPS + (size_t)seg * SEGT;
    const float* xp = g_xp + row0 * NH;
    float*       hs = hseq + row0 * NH;

    uint64_t w[64];
#pragma unroll
    for (int k = 0; k < 64; k++)
        w[k] = *reinterpret_cast<const uint64_t*>(&W1[(size_t)j * 256 + 2 * k]);  // W1h = W1[:, :128]

    hbuf[0][j] = (seg == 0) ? 0.0f : g_hstate[b * NH + j];

    float xr[8];
#pragma unroll
    for (int u = 0; u < 8; u++)
        xr[u] = xp[(size_t)u * NH + j];

    for (int t0 = 0; t0 < SEGT; t0 += 8) {
#pragma unroll
        for (int u = 0; u < 8; u++) {
            const int t = t0 + u;
            __syncthreads();                 // h_t visible; WAR safe
            const float* hp = hbuf[u & 1];   // t&1 == u&1
            uint64_t a0 = 0, a1 = 0, a2 = 0, a3 = 0;
#pragma unroll
            for (int k = 0; k < 16; k++) {
                ulonglong2 h0 = *reinterpret_cast<const ulonglong2*>(&hp[8 * k]);
                ulonglong2 h1 = *reinterpret_cast<const ulonglong2*>(&hp[8 * k + 4]);
                a0 = ffma2(w[4 * k],     h0.x, a0);
                a1 = ffma2(w[4 * k + 1], h0.y, a1);
                a2 = ffma2(w[4 * k + 2], h1.x, a2);
                a3 = ffma2(w[4 * k + 3], h1.y, a3);
            }
            float s = (f2sum(a0) + f2sum(a1)) + (f2sum(a2) + f2sum(a3)) + xr[u];
            s = fmaxf(s, 0.0f);
            hbuf[(u + 1) & 1][j] = s;        // next step's input (SMEM)
            hs[(size_t)t * NH + j] = s;      // for output projection
            xr[u] = xp[(size_t)(t + 8) * NH + j];   // refill ring (padded)
        }
    }
    __syncthreads();
    g_hstate[b * NH + j] = hbuf[0][j];       // SEGT even -> state lives in buf 0
}

// ---------------------------------------------------------------------------
// Launch: coarse 2-segment software pipeline, monolithic-width chunks.
//   g1A -> [scanA || g1B(sB)] -> [scanB || g2A(sC)] -> g2B -> join
// ---------------------------------------------------------------------------
extern "C" void kernel_launch(void* const* d_in, const int* in_sizes, int n_in,
                              void* d_out, int out_size)
{
    const float* input = (const float*)d_in[0];   // (64, 4096, 128)
    const float* W1    = (const float*)d_in[1];   // (128, 256)
    const float* b1    = (const float*)d_in[2];   // (128,)
    const float* W2    = (const float*)d_in[3];   // (128, 128)
    const float* b2    = (const float*)d_in[4];   // (128,)
    float* out = (float*)d_out;

    float *xp_ptr, *h_ptr;
    cudaGetSymbolAddress((void**)&xp_ptr, g_xp);
    cudaGetSymbolAddress((void**)&h_ptr,  g_h);

    cudaFuncSetAttribute(rnn_scan_kernel,
                         cudaFuncAttributeMaxDynamicSharedMemorySize, SCAN_SMEM);

    static cudaStream_t sB = nullptr, sC = nullptr;
    static cudaEvent_t eFork, eB, esA, eC;
    if (sB == nullptr) {
        cudaStreamCreateWithFlags(&sB, cudaStreamNonBlocking);
        cudaStreamCreateWithFlags(&sC, cudaStreamNonBlocking);
        cudaEventCreateWithFlags(&eFork, cudaEventDisableTiming);
        cudaEventCreateWithFlags(&eB,    cudaEventDisableTiming);
        cudaEventCreateWithFlags(&esA,   cudaEventDisableTiming);
        cudaEventCreateWithFlags(&eC,    cudaEventDisableTiming);
    }

    const int nchunk_half = SEGT / RPB;       // 8  -> grid 512 per half
    const int grid_half = BATCH * nchunk_half;

    // g1A: xp for t in [0, 2048)  (full-width grid, default stream)
    gemm128_kernel<false><<<grid_half, 128>>>(input, W1, 256, 128, b1, xp_ptr, 0, nchunk_half);
    cudaEventRecord(eFork, 0);

    // g1B: xp for t in [2048, 4096) on sB, concurrent with scanA
    cudaStreamWaitEvent(sB, eFork, 0);
    gemm128_kernel<false><<<grid_half, 128, 0, sB>>>(input, W1, 256, 128, b1, xp_ptr, SEGT, nchunk_half);
    cudaEventRecord(eB, sB);

    // scanA (t in [0, 2048)), SM-exclusive via huge dynamic smem
    rnn_scan_kernel<<<BATCH, 128, SCAN_SMEM>>>(W1, h_ptr, 0);
    cudaEventRecord(esA, 0);

    // g2A: out for t in [0, 2048) on sC, concurrent with scanB
    cudaStreamWaitEvent(sC, esA, 0);
    gemm128_kernel<true><<<grid_half, 128, 0, sC>>>(h_ptr, W2, 128, 0, b2, out, 0, nchunk_half);
    cudaEventRecord(eC, sC);

    // scanB (t in [2048, 4096)) after g1B
    cudaStreamWaitEvent(0, eB, 0);
    rnn_scan_kernel<<<BATCH, 128, SCAN_SMEM>>>(W1, h_ptr, 1);

    // g2B: out for t in [2048, 4096) (default stream, tail)
    gemm128_kernel<true><<<grid_half, 128>>>(h_ptr, W2, 128, 0, b2, out, SEGT, nchunk_half);

    // join sC
    cudaStreamWaitEvent(0, eC, 0);
}

// round 8
// speedup vs baseline: 2.7290x; 1.2983x over previous
#include <cuda_runtime.h>
#include <cstdint>

#define T_STEPS 4096
#define BATCH   64
#define NH      128
#define NROWS   (BATCH * T_STEPS)   // 262144
#define SEGT    2048                // steps per scan half
#define SCAN_SMEM (216 * 1024)      // blocks GEMM CTA co-residency on scan SMs

// Scratch (allocation-free rule: __device__ globals).
__device__ float g_xp[((size_t)NROWS + 8) * NH];   // padded for scan LDG ring
__device__ float g_h [(size_t)NROWS * NH];
__device__ float g_hstate[BATCH * NH];
__device__ float g_w1t[NH * NH];    // W1x^T : [k][j]
__device__ float g_w2t[NH * NH];    // W2^T  : [k][j]

// ---------------------------------------------------------------------------
// Helpers
// ---------------------------------------------------------------------------
__device__ __forceinline__ uint64_t ffma2(uint64_t a, uint64_t b, uint64_t c) {
    uint64_t d;
    asm("fma.rn.f32x2 %0, %1, %2, %3;" : "=l"(d) : "l"(a), "l"(b), "l"(c));
    return d;
}
__device__ __forceinline__ uint64_t addf2(uint64_t a, uint64_t b) {
    uint64_t d;
    asm("add.rn.f32x2 %0, %1, %2;" : "=l"(d) : "l"(a), "l"(b));
    return d;
}
__device__ __forceinline__ float f2sum(uint64_t v) {
    float lo = __uint_as_float((uint32_t)v);
    float hi = __uint_as_float((uint32_t)(v >> 32));
    return lo + hi;
}
__device__ __forceinline__ uint64_t packf2(float x) {
    uint64_t d;
    asm("mov.b64 %0, {%1, %1};" : "=l"(d) : "f"(x));
    return d;
}
__device__ __forceinline__ void cp_async16(uint32_t saddr, const void* g) {
    asm volatile("cp.async.cg.shared.global [%0], [%1], 16;" :: "r"(saddr), "l"(g));
}
__device__ __forceinline__ void cp_commit() { asm volatile("cp.async.commit_group;"); }
__device__ __forceinline__ void cp_wait1()  { asm volatile("cp.async.wait_group 1;" ::: "memory"); }

// ---------------------------------------------------------------------------
// Setup: W transposes.  Wt1[k][j] = W1[j][128+k],  Wt2[k][j] = W2[j][k]
// ---------------------------------------------------------------------------
__global__ void transpose_w_kernel(const float* __restrict__ W1,
                                   const float* __restrict__ W2)
{
    const int j = threadIdx.x;        // 128
    const int k = blockIdx.x;         // 128
    g_w1t[k * NH + j] = W1[j * 256 + NH + k];
    g_w2t[k * NH + j] = W2[j * NH + k];
}

// ---------------------------------------------------------------------------
// Tiled SGEMM: out[row, j] = (relu?)( sum_k A[row,k] * Wt[k,j] + bias[j] )
// CTA: 128 rows x 128 cols, 256 threads (16x16), 8x8 tile per thread.
// K = 128 in 8 panels of 16, double-buffered cp.async.
// ---------------------------------------------------------------------------
#define GR 128          // rows per CTA
#define GK 16           // k-panel depth
#define ASTRIDE 20      // padded floats per As row (80B, 16B-aligned, no conflicts)

template<bool RELU>
__global__ void __launch_bounds__(256, 2) gemm_tiled_kernel(
    const float* __restrict__ A, const float* __restrict__ Wt,
    const float* __restrict__ bias, float* __restrict__ out,
    int t_off, int nchunk)
{
    __shared__ __align__(16) float As[2][GR][ASTRIDE];  // 20 KB
    __shared__ __align__(16) float Bs[2][GK][NH];       // 16 KB

    const int tid = threadIdx.x;
    const int tx = tid & 15;          // col group (8 cols)
    const int ty = tid >> 4;          // row group (8 rows)
    const int b  = blockIdx.x / nchunk;
    const int ch = blockIdx.x % nchunk;
    const size_t base = (size_t)b * T_STEPS + (size_t)t_off + (size_t)ch * GR;
    const float* Ag = A + base * NH;

    const uint32_t sA = (uint32_t)__cvta_generic_to_shared(&As[0][0][0]);
    const uint32_t sB = (uint32_t)__cvta_generic_to_shared(&Bs[0][0][0]);

    // cp.async index plan: 2 x 16B per thread per tensor per panel.
    //   A: 512 cp: idx -> row = idx/4, sub = idx%4 ; src A[row, p*16 + sub*4]
    //   B: 512 cp: idx -> kk  = idx/32, sub = idx%32; src Wt[(p*16+kk)*128 + sub*4]
    auto load_panel = [&](int p, int buf) {
#pragma unroll
        for (int q = 0; q < 2; q++) {
            int idx = tid * 2 + q;
            int row = idx >> 2, sub = idx & 3;
            cp_async16(sA + (uint32_t)(buf * GR * ASTRIDE + row * ASTRIDE + sub * 4) * 4,
                       Ag + (size_t)row * NH + p * GK + sub * 4);
        }
#pragma unroll
        for (int q = 0; q < 2; q++) {
            int idx = tid * 2 + q;
            int kk = idx >> 5, sub = idx & 31;
            cp_async16(sB + (uint32_t)(buf * GK * NH + kk * NH + sub * 4) * 4,
                       Wt + (size_t)(p * GK + kk) * NH + sub * 4);
        }
    };

    uint64_t acc[8][4];
#pragma unroll
    for (int r = 0; r < 8; r++)
#pragma unroll
        for (int c = 0; c < 4; c++) acc[r][c] = 0;

    load_panel(0, 0);
    cp_commit();

#pragma unroll
    for (int p = 0; p < 8; p++) {
        if (p < 7) load_panel(p + 1, (p + 1) & 1);
        cp_commit();
        cp_wait1();
        __syncthreads();

        const int buf = p & 1;
#pragma unroll
        for (int kk = 0; kk < GK; kk++) {
            const float* brow = &Bs[buf][kk][tx * 8];
            ulonglong2 bp0 = *reinterpret_cast<const ulonglong2*>(brow);
            ulonglong2 bp1 = *reinterpret_cast<const ulonglong2*>(brow + 4);
#pragma unroll
            for (int r = 0; r < 8; r++) {
                uint64_t ap = packf2(As[buf][ty * 8 + r][kk]);
                acc[r][0] = ffma2(ap, bp0.x, acc[r][0]);
                acc[r][1] = ffma2(ap, bp0.y, acc[r][1]);
                acc[r][2] = ffma2(ap, bp1.x, acc[r][2]);
                acc[r][3] = ffma2(ap, bp1.y, acc[r][3]);
            }
        }
        __syncthreads();
    }

    // epilogue: + bias, relu, store
    float4 bv0 = *reinterpret_cast<const float4*>(&bias[tx * 8]);
    float4 bv1 = *reinterpret_cast<const float4*>(&bias[tx * 8 + 4]);
#pragma unroll
    for (int r = 0; r < 8; r++) {
        float2 c0 = *reinterpret_cast<float2*>(&acc[r][0]);
        float2 c1 = *reinterpret_cast<float2*>(&acc[r][1]);
        float2 c2 = *reinterpret_cast<float2*>(&acc[r][2]);
        float2 c3 = *reinterpret_cast<float2*>(&acc[r][3]);
        float4 o0 = make_float4(c0.x + bv0.x, c0.y + bv0.y, c1.x + bv0.z, c1.y + bv0.w);
        float4 o1 = make_float4(c2.x + bv1.x, c2.y + bv1.y, c3.x + bv1.z, c3.y + bv1.w);
        if (RELU) {
            o0.x = fmaxf(o0.x, 0.f); o0.y = fmaxf(o0.y, 0.f);
            o0.z = fmaxf(o0.z, 0.f); o0.w = fmaxf(o0.w, 0.f);
            o1.x = fmaxf(o1.x, 0.f); o1.y = fmaxf(o1.y, 0.f);
            o1.z = fmaxf(o1.z, 0.f); o1.w = fmaxf(o1.w, 0.f);
        }
        float* op = out + (base + ty * 8 + r) * NH + tx * 8;
        *reinterpret_cast<float4*>(op)     = o0;
        *reinterpret_cast<float4*>(op + 4) = o1;
    }
}

// ---------------------------------------------------------------------------
// Scan half: 2048 steps of h_t = relu(W1h @ h_{t-1} + xp_t).
// 64 blocks, 128 threads, thread j owns W1h row j (64 x f32x2 in regs).
// Inner product is explicitly software-pipelined: 4 groups of 8 x LDS.128,
// register double-buffered, so LDS latency overlaps the FMA chain.
// ---------------------------------------------------------------------------
__global__ void __launch_bounds__(128, 1) rnn_scan_kernel(
    const float* __restrict__ W1, float* __restrict__ hseq, int seg)
{
    extern __shared__ __align__(16) float dyn[];
    float (*hbuf)[NH] = reinterpret_cast<float (*)[NH]>(dyn);

    const int j = threadIdx.x;
    const int b = blockIdx.x;

    const size_t row0 = (size_t)b * T_STEPS + (size_t)seg * SEGT;
    const float* xp = g_xp + row0 * NH;
    float*       hs = hseq + row0 * NH;

    uint64_t w[64];
#pragma unroll
    for (int k = 0; k < 64; k++)
        w[k] = *reinterpret_cast<const uint64_t*>(&W1[(size_t)j * 256 + 2 * k]);  // W1h

    hbuf[0][j] = (seg == 0) ? 0.0f : g_hstate[b * NH + j];

    float xr[8];
#pragma unroll
    for (int u = 0; u < 8; u++)
        xr[u] = xp[(size_t)u * NH + j];

    for (int t0 = 0; t0 < SEGT; t0 += 8) {
#pragma unroll
        for (int u = 0; u < 8; u++) {
            const int t = t0 + u;
            __syncthreads();
            const ulonglong2* hp = reinterpret_cast<const ulonglong2*>(hbuf[u & 1]);

            ulonglong2 hva[8], hvb[8];
#pragma unroll
            for (int k = 0; k < 8; k++) hva[k] = hp[k];          // group 0 in flight

            uint64_t a0 = 0, a1 = 0, a2 = 0, a3 = 0;
#pragma unroll
            for (int g = 0; g < 4; g++) {
                const ulonglong2* cur = (g & 1) ? hvb : hva;
                ulonglong2*       nxt = (g & 1) ? hva : hvb;
                if (g < 3) {
#pragma unroll
                    for (int k = 0; k < 8; k++) nxt[k] = hp[8 * (g + 1) + k];  // prefetch
                }
#pragma unroll
                for (int k = 0; k < 8; k++) {                    // 16 FFMA2
                    a0 = ffma2(w[16 * g + 2 * k],     cur[k].x, a0);
                    a1 = ffma2(w[16 * g + 2 * k + 1], cur[k].y, a1);
                }
                // rotate chains across groups for depth 4 per acc
                uint64_t tmp = a0; a0 = a2; a2 = tmp;
                tmp = a1; a1 = a3; a3 = tmp;
            }
            uint64_t asum = addf2(addf2(a0, a1), addf2(a2, a3));
            float s = f2sum(asum) + xr[u];
            s = fmaxf(s, 0.0f);
            hbuf[(u + 1) & 1][j] = s;
            hs[(size_t)t * NH + j] = s;
            xr[u] = xp[(size_t)(t + 8) * NH + j];   // refill ring (padded)
        }
    }
    __syncthreads();
    g_hstate[b * NH + j] = hbuf[0][j];       // SEGT even
}

// ---------------------------------------------------------------------------
// Launch. Order matters: scan kernels are enqueued BEFORE the GEMMs that
// overlap them, so the scan's 216KB CTAs claim their SMs first; GEMM CTAs
// (37KB) then cannot co-reside there (228-216 < 37).
//   transpose -> g1A -> [scanA || g1B(sB)] -> [scanB || g2A(sC)] -> g2B
// ---------------------------------------------------------------------------
extern "C" void kernel_launch(void* const* d_in, const int* in_sizes, int n_in,
                              void* d_out, int out_size)
{
    const float* input = (const float*)d_in[0];   // (64, 4096, 128)
    const float* W1    = (const float*)d_in[1];   // (128, 256)
    const float* b1    = (const float*)d_in[2];   // (128,)
    const float* W2    = (const float*)d_in[3];   // (128, 128)
    const float* b2    = (const float*)d_in[4];   // (128,)
    float* out = (float*)d_out;

    float *xp_ptr, *h_ptr, *w1t_ptr, *w2t_ptr;
    cudaGetSymbolAddress((void**)&xp_ptr,  g_xp);
    cudaGetSymbolAddress((void**)&h_ptr,   g_h);
    cudaGetSymbolAddress((void**)&w1t_ptr, g_w1t);
    cudaGetSymbolAddress((void**)&w2t_ptr, g_w2t);

    cudaFuncSetAttribute(rnn_scan_kernel,
                         cudaFuncAttributeMaxDynamicSharedMemorySize, SCAN_SMEM);

    static cudaStream_t sB = nullptr, sC = nullptr;
    static cudaEvent_t eFork, eB, esA, eC;
    if (sB == nullptr) {
        cudaStreamCreateWithFlags(&sB, cudaStreamNonBlocking);
        cudaStreamCreateWithFlags(&sC, cudaStreamNonBlocking);
        cudaEventCreateWithFlags(&eFork, cudaEventDisableTiming);
        cudaEventCreateWithFlags(&eB,    cudaEventDisableTiming);
        cudaEventCreateWithFlags(&esA,   cudaEventDisableTiming);
        cudaEventCreateWithFlags(&eC,    cudaEventDisableTiming);
    }

    const int nchunk = SEGT / GR;            // 16 -> 1024 blocks per half
    const int grid_half = BATCH * nchunk;

    // setup + g1A on default stream
    transpose_w_kernel<<<NH, NH>>>(W1, W2);
    gemm_tiled_kernel<false><<<grid_half, 256>>>(input, w1t_ptr, b1, xp_ptr, 0, nchunk);
    cudaEventRecord(eFork, 0);

    // scanA enqueued FIRST so its CTAs claim SMs before g1B's
    rnn_scan_kernel<<<BATCH, 128, SCAN_SMEM>>>(W1, h_ptr, 0);
    cudaEventRecord(esA, 0);

    // g1B overlaps scanA on the other ~84 SMs
    cudaStreamWaitEvent(sB, eFork, 0);
    gemm_tiled_kernel<false><<<grid_half, 256, 0, sB>>>(input, w1t_ptr, b1, xp_ptr, SEGT, nchunk);
    cudaEventRecord(eB, sB);

    // scanB after g1B; enqueued before g2A
    cudaStreamWaitEvent(0, eB, 0);
    rnn_scan_kernel<<<BATCH, 128, SCAN_SMEM>>>(W1, h_ptr, 1);

    // g2A overlaps scanB
    cudaStreamWaitEvent(sC, esA, 0);
    gemm_tiled_kernel<true><<<grid_half, 256, 0, sC>>>(h_ptr, w2t_ptr, b2, out, 0, nchunk);
    cudaEventRecord(eC, sC);

    // g2B tail on default stream
    gemm_tiled_kernel<true><<<grid_half, 256>>>(h_ptr, w2t_ptr, b2, out, SEGT, nchunk);

    // join
    cudaStreamWaitEvent(0, eC, 0);
}